// round 1
// baseline (speedup 1.0000x reference)
#include <cuda_runtime.h>
#include <cuda_bf16.h>
#include <math.h>

// ---------------------------------------------------------------------------
// Problem constants
// ---------------------------------------------------------------------------
#define S 2048
#define HIDDEN 2048
#define Q_LORA 1536
#define KV_LORA 512
#define NOPE 128
#define ROPE 64
#define V_DIM 128
#define NH 16
#define QK 192          // NOPE + ROPE
#define KVD 256         // NOPE + V_DIM
#define EPSV 1e-6f

// ---------------------------------------------------------------------------
// Scratch (static device globals; allocation inside kernel_launch is banned)
// ---------------------------------------------------------------------------
__device__ float g_qc    [(size_t)S * Q_LORA];          // 12.6 MB
__device__ float g_q     [(size_t)S * NH * QK];         // 25 MB (q_full after RoPE)
__device__ float g_kvc   [(size_t)S * (KV_LORA + ROPE)];// 4.7 MB
__device__ float g_kvlat [(size_t)S * KV_LORA];         // 4.2 MB
__device__ float g_kv    [(size_t)S * NH * KVD];        // 33.5 MB (k_nope | v)
__device__ float g_krope [(size_t)S * ROPE];            // 0.5 MB
__device__ float g_kfull [(size_t)S * NH * QK];         // 25 MB
__device__ float g_scores[(size_t)NH * S * S];          // 268 MB
__device__ float g_attn  [(size_t)S * NH * V_DIM];      // 16.8 MB

// ---------------------------------------------------------------------------
// Generic tiled SGEMM: C[M,N] = alpha * A[M,K] @ op(B), row-major.
// TRANSB:   B is [N,K] row-major (C = alpha * A @ B^T)
// CAUSAL_SKIP: skip blocks strictly above the diagonal (scores GEMM)
// CAUSAL_K:    truncate K loop at bm+BM (PV GEMM; probs are zero past diag)
// BM=BN=128, BK=8, 256 threads, 8x8 per-thread register tile.
// Requirements: M % 128 == 0, K % 8 == 0 (N handled with guards).
// ---------------------------------------------------------------------------
#define BM 128
#define BN 128
#define BK 8
#define TM 8
#define TN 8

template <bool TRANSB, bool CAUSAL_SKIP, bool CAUSAL_K>
__global__ __launch_bounds__(256) void gemm_kernel(
    const float* __restrict__ A, int lda, long long strideA,
    const float* __restrict__ B, int ldb, long long strideB,
    float* __restrict__ C, int ldc, long long strideC,
    int M, int N, int K, float alpha)
{
    const int bm = blockIdx.y * BM;
    const int bn = blockIdx.x * BN;
    if (CAUSAL_SKIP && bn >= bm + BM) return;   // fully masked tile

    const int batch = blockIdx.z;
    A += (long long)batch * strideA;
    B += (long long)batch * strideB;
    C += (long long)batch * strideC;

    int Keff = K;
    if (CAUSAL_K) Keff = min(K, bm + BM);

    __shared__ float As[BK][BM];
    __shared__ float Bs[BK][BN];

    const int tid = threadIdx.x;
    const int tx = tid & 15;
    const int ty = tid >> 4;
    const int row0 = ty * TM;
    const int col0 = tx * TN;
    const bool nfull = (bn + BN <= N);

    float acc[TM][TN];
#pragma unroll
    for (int i = 0; i < TM; i++)
#pragma unroll
        for (int j = 0; j < TN; j++) acc[i][j] = 0.f;

    for (int k0 = 0; k0 < Keff; k0 += BK) {
        // --- load A tile (always full): BM x BK, float4 along K ---
        {
            int idx = tid * 4;
            int r = idx >> 3;       // 0..127
            int c = idx & 7;        // 0 or 4
            float4 v = *reinterpret_cast<const float4*>(
                A + (long long)(bm + r) * lda + k0 + c);
            As[c + 0][r] = v.x; As[c + 1][r] = v.y;
            As[c + 2][r] = v.z; As[c + 3][r] = v.w;
        }
        // --- load B tile ---
        if (!TRANSB) {
            int idx = tid * 4;
            int r = idx >> 7;       // 0..7
            int c = idx & 127;
            if (nfull) {
                float4 v = *reinterpret_cast<const float4*>(
                    B + (long long)(k0 + r) * ldb + bn + c);
                Bs[r][c + 0] = v.x; Bs[r][c + 1] = v.y;
                Bs[r][c + 2] = v.z; Bs[r][c + 3] = v.w;
            } else {
#pragma unroll
                for (int j = 0; j < 4; j++) {
                    int cc = c + j;
                    Bs[r][cc] = (bn + cc < N)
                        ? B[(long long)(k0 + r) * ldb + bn + cc] : 0.f;
                }
            }
        } else {
            int idx = tid * 4;
            int r = idx >> 3;       // n index 0..127
            int c = idx & 7;        // k: 0 or 4
            if (bn + r < N) {
                float4 v = *reinterpret_cast<const float4*>(
                    B + (long long)(bn + r) * ldb + k0 + c);
                Bs[c + 0][r] = v.x; Bs[c + 1][r] = v.y;
                Bs[c + 2][r] = v.z; Bs[c + 3][r] = v.w;
            } else {
                Bs[c + 0][r] = 0.f; Bs[c + 1][r] = 0.f;
                Bs[c + 2][r] = 0.f; Bs[c + 3][r] = 0.f;
            }
        }
        __syncthreads();

#pragma unroll
        for (int kk = 0; kk < BK; kk++) {
            float4 a0 = *reinterpret_cast<const float4*>(&As[kk][row0]);
            float4 a1 = *reinterpret_cast<const float4*>(&As[kk][row0 + 4]);
            float4 b0 = *reinterpret_cast<const float4*>(&Bs[kk][col0]);
            float4 b1 = *reinterpret_cast<const float4*>(&Bs[kk][col0 + 4]);
            float ra[TM] = {a0.x, a0.y, a0.z, a0.w, a1.x, a1.y, a1.z, a1.w};
            float rb[TN] = {b0.x, b0.y, b0.z, b0.w, b1.x, b1.y, b1.z, b1.w};
#pragma unroll
            for (int i = 0; i < TM; i++)
#pragma unroll
                for (int j = 0; j < TN; j++)
                    acc[i][j] += ra[i] * rb[j];
        }
        __syncthreads();
    }

    // --- write C ---
#pragma unroll
    for (int i = 0; i < TM; i++) {
        int r = bm + row0 + i;
#pragma unroll
        for (int j = 0; j < TN; j += 4) {
            int c = bn + col0 + j;
            if (nfull) {
                float4 v = make_float4(acc[i][j] * alpha, acc[i][j + 1] * alpha,
                                       acc[i][j + 2] * alpha, acc[i][j + 3] * alpha);
                *reinterpret_cast<float4*>(C + (long long)r * ldc + c) = v;
            } else {
#pragma unroll
                for (int jj = 0; jj < 4; jj++)
                    if (c + jj < N)
                        C[(long long)r * ldc + c + jj] = acc[i][j + jj] * alpha;
            }
        }
    }
}

// ---------------------------------------------------------------------------
// RMSNorm: one block per row
// ---------------------------------------------------------------------------
__global__ __launch_bounds__(256) void rmsnorm_kernel(
    const float* __restrict__ in, int ldin,
    float* __restrict__ out, int ldout,
    const float* __restrict__ w, int cols)
{
    const int r = blockIdx.x;
    const float* x = in + (long long)r * ldin;
    float ss = 0.f;
    for (int c = threadIdx.x; c < cols; c += blockDim.x) {
        float v = x[c];
        ss += v * v;
    }
    __shared__ float sh[256];
    sh[threadIdx.x] = ss;
    __syncthreads();
    for (int s = 128; s > 0; s >>= 1) {
        if (threadIdx.x < s) sh[threadIdx.x] += sh[threadIdx.x + s];
        __syncthreads();
    }
    float scale = rsqrtf(sh[0] / (float)cols + EPSV);
    for (int c = threadIdx.x; c < cols; c += blockDim.x)
        out[(long long)r * ldout + c] = x[c] * scale * w[c];
}

// ---------------------------------------------------------------------------
// RoPE (interleaved): rotates q's rope part in place, emits rotated k_rope.
// One block per position s, 512 threads = 16 heads x 32 pairs.
// ---------------------------------------------------------------------------
__global__ __launch_bounds__(512) void rope_kernel(
    float* __restrict__ q, const float* __restrict__ kvc,
    float* __restrict__ krope, const int* __restrict__ positions)
{
    const int s = blockIdx.x;
    const int t = threadIdx.x;
    const int h = t >> 5;
    const int i = t & 31;

    float pos = (float)positions[s];
    float inv = powf(10000.0f, -(2.0f * (float)i) / (float)ROPE);
    float ang = pos * inv;
    float sn, cs;
    sincosf(ang, &sn, &cs);

    float* qp = q + ((long long)s * NH + h) * QK + NOPE + 2 * i;
    float x1 = qp[0], x2 = qp[1];
    qp[0] = x1 * cs - x2 * sn;
    qp[1] = x2 * cs + x1 * sn;

    if (h == 0) {
        const float* kp = kvc + (long long)s * (KV_LORA + ROPE) + KV_LORA + 2 * i;
        float y1 = kp[0], y2 = kp[1];
        krope[(long long)s * ROPE + 2 * i]     = y1 * cs - y2 * sn;
        krope[(long long)s * ROPE + 2 * i + 1] = y2 * cs + y1 * sn;
    }
}

// ---------------------------------------------------------------------------
// Assemble k_full[s][h][0:192] = k_nope[s][h][0:128] | k_rope_rot[s][0:64]
// ---------------------------------------------------------------------------
__global__ __launch_bounds__(256) void kfull_kernel(
    const float* __restrict__ kv, const float* __restrict__ krope,
    float* __restrict__ kfull)
{
    long long idx = (long long)blockIdx.x * blockDim.x + threadIdx.x;
    const long long total = (long long)S * NH * QK;
    if (idx >= total) return;
    int d = (int)(idx % QK);
    long long sh = idx / QK;
    int h = (int)(sh % NH);
    long long s = sh / NH;
    kfull[idx] = (d < NOPE) ? kv[(s * NH + h) * KVD + d]
                            : krope[s * ROPE + (d - NOPE)];
}

// ---------------------------------------------------------------------------
// Causal softmax over scores[h][s][*]: in place; zeros past the diagonal.
// Grid (S, NH), 256 threads.
// ---------------------------------------------------------------------------
__global__ __launch_bounds__(256) void softmax_kernel(float* __restrict__ scores)
{
    const int s = blockIdx.x;
    const int h = blockIdx.y;
    float* row = scores + ((long long)h * S + s) * S;
    const int L = s + 1;
    __shared__ float sh[256];

    float m = -3.4e38f;
    for (int t = threadIdx.x; t < L; t += blockDim.x) m = fmaxf(m, row[t]);
    sh[threadIdx.x] = m;
    __syncthreads();
    for (int k = 128; k > 0; k >>= 1) {
        if (threadIdx.x < k) sh[threadIdx.x] = fmaxf(sh[threadIdx.x], sh[threadIdx.x + k]);
        __syncthreads();
    }
    m = sh[0];
    __syncthreads();

    float sum = 0.f;
    for (int t = threadIdx.x; t < L; t += blockDim.x) {
        float e = __expf(row[t] - m);
        row[t] = e;
        sum += e;
    }
    sh[threadIdx.x] = sum;
    __syncthreads();
    for (int k = 128; k > 0; k >>= 1) {
        if (threadIdx.x < k) sh[threadIdx.x] += sh[threadIdx.x + k];
        __syncthreads();
    }
    float inv = 1.0f / sh[0];

    for (int t = threadIdx.x; t < S; t += blockDim.x)
        row[t] = (t < L) ? row[t] * inv : 0.f;
}

// ---------------------------------------------------------------------------
// Host launcher
// ---------------------------------------------------------------------------
static inline void* sym_addr(const void* symbol)
{
    void* p = nullptr;
    cudaGetSymbolAddress(&p, symbol);
    return p;
}

extern "C" void kernel_launch(void* const* d_in, const int* in_sizes, int n_in,
                              void* d_out, int out_size)
{
    const float* hidden  = (const float*)d_in[0];
    const float* w_qa    = (const float*)d_in[1];
    const float* qa_ln_w = (const float*)d_in[2];
    const float* w_qb    = (const float*)d_in[3];
    const float* w_kva   = (const float*)d_in[4];
    const float* kva_ln_w= (const float*)d_in[5];
    const float* w_kvb   = (const float*)d_in[6];
    const float* w_o     = (const float*)d_in[7];
    const int*   positions = (const int*)d_in[8];
    float* out = (float*)d_out;

    float* qc     = (float*)sym_addr(g_qc);
    float* q      = (float*)sym_addr(g_q);
    float* kvc    = (float*)sym_addr(g_kvc);
    float* kvlat  = (float*)sym_addr(g_kvlat);
    float* kv     = (float*)sym_addr(g_kv);
    float* krope  = (float*)sym_addr(g_krope);
    float* kfull  = (float*)sym_addr(g_kfull);
    float* scores = (float*)sym_addr(g_scores);
    float* attn   = (float*)sym_addr(g_attn);

    const dim3 blk(256);

    // 1. q_c_raw = hidden @ w_qa            [2048,1536] K=2048
    gemm_kernel<false, false, false><<<dim3(Q_LORA / BN, S / BM, 1), blk>>>(
        hidden, HIDDEN, 0, w_qa, Q_LORA, 0, qc, Q_LORA, 0,
        S, Q_LORA, HIDDEN, 1.0f);

    // 2. rmsnorm(q_c) in place
    rmsnorm_kernel<<<S, blk>>>(qc, Q_LORA, qc, Q_LORA, qa_ln_w, Q_LORA);

    // 3. q = q_c @ w_qb                     [2048,3072] K=1536
    gemm_kernel<false, false, false><<<dim3((NH * QK) / BN, S / BM, 1), blk>>>(
        qc, Q_LORA, 0, w_qb, NH * QK, 0, q, NH * QK, 0,
        S, NH * QK, Q_LORA, 1.0f);

    // 4. kv_c = hidden @ w_kva              [2048,576] K=2048 (partial N tile)
    gemm_kernel<false, false, false><<<dim3((KV_LORA + ROPE + BN - 1) / BN, S / BM, 1), blk>>>(
        hidden, HIDDEN, 0, w_kva, KV_LORA + ROPE, 0, kvc, KV_LORA + ROPE, 0,
        S, KV_LORA + ROPE, HIDDEN, 1.0f);

    // 5. kv_lat = rmsnorm(kv_c[:, :512])
    rmsnorm_kernel<<<S, blk>>>(kvc, KV_LORA + ROPE, kvlat, KV_LORA, kva_ln_w, KV_LORA);

    // 6. kv = kv_lat @ w_kvb                [2048,4096] K=512
    gemm_kernel<false, false, false><<<dim3((NH * KVD) / BN, S / BM, 1), blk>>>(
        kvlat, KV_LORA, 0, w_kvb, NH * KVD, 0, kv, NH * KVD, 0,
        S, NH * KVD, KV_LORA, 1.0f);

    // 7. RoPE (q in place; k_rope -> krope)
    rope_kernel<<<S, 512>>>(q, kvc, krope, positions);

    // 8. assemble k_full
    {
        long long total = (long long)S * NH * QK;
        int nb = (int)((total + 255) / 256);
        kfull_kernel<<<nb, blk>>>(kv, krope, kfull);
    }

    // 9. scores[h] = (Q_h @ K_h^T) * scale   batched NT, causal tile skip
    const float scale = 1.0f / sqrtf((float)QK);
    gemm_kernel<true, true, false><<<dim3(S / BN, S / BM, NH), blk>>>(
        q, NH * QK, QK,            // A: q + h*192, lda 3072
        kfull, NH * QK, QK,        // B: kfull + h*192 (transposed)
        scores, S, (long long)S * S,
        S, S, QK, scale);

    // 10. causal softmax in place (writes zeros past the diagonal)
    softmax_kernel<<<dim3(S, NH), blk>>>(scores);

    // 11. attn[h] = probs[h] @ V_h           batched NN, causal-K truncation
    gemm_kernel<false, false, true><<<dim3(V_DIM / BN, S / BM, NH), blk>>>(
        scores, S, (long long)S * S,
        kv + NOPE, NH * KVD, KVD,  // B: kv + h*256 + 128, ldb 4096
        attn, NH * V_DIM, V_DIM,
        S, V_DIM, S, 1.0f);

    // 12. out = attn @ w_o                   [2048,2048] K=2048
    gemm_kernel<false, false, false><<<dim3(HIDDEN / BN, S / BM, 1), blk>>>(
        attn, NH * V_DIM, 0, w_o, HIDDEN, 0, out, HIDDEN, 0,
        S, HIDDEN, NH * V_DIM, 1.0f);
}

// round 2
// speedup vs baseline: 2.9231x; 2.9231x over previous
#include <cuda_runtime.h>
#include <cuda_bf16.h>
#include <math.h>

// ---------------------------------------------------------------------------
// Problem constants
// ---------------------------------------------------------------------------
#define S 2048
#define HIDDEN 2048
#define Q_LORA 1536
#define KV_LORA 512
#define NOPE 128
#define ROPE 64
#define V_DIM 128
#define NH 16
#define QK 192          // NOPE + ROPE
#define KVD 256         // NOPE + V_DIM
#define EPSV 1e-6f

// ---------------------------------------------------------------------------
// Scratch (static device globals; allocation inside kernel_launch is banned)
// ---------------------------------------------------------------------------
__device__ float g_qc    [(size_t)S * Q_LORA];
__device__ float g_q     [(size_t)S * NH * QK];
__device__ float g_kvc   [(size_t)S * (KV_LORA + ROPE)];
__device__ float g_kvlat [(size_t)S * KV_LORA];
__device__ float g_kv    [(size_t)S * NH * KVD];
__device__ float g_krope [(size_t)S * ROPE];
__device__ float g_kfull [(size_t)S * NH * QK];
__device__ float g_scores[(size_t)NH * S * S];
__device__ float g_attn  [(size_t)S * NH * V_DIM];

// ---------------------------------------------------------------------------
// tf32 tensor-core GEMM: C[M,N] = alpha * A[M,K] @ op(B), row-major.
// TRANSB:      B is [N,K] row-major (C = alpha * A @ B^T)
// CAUSAL_SKIP: skip CTA tiles strictly above the diagonal (scores GEMM)
// CAUSAL_K:    truncate K loop at bm+BM (PV GEMM; probs zero past diagonal)
//
// CTA tile 128x128x32, 256 threads = 8 warps in a 4(m) x 2(n) layout,
// warp tile 32x64 built from m16n8k8 tf32 mma.sync. 2-stage cp.async pipeline.
// Requirements: M % 128 == 0, K % 32 == 0 (Keff multiple of 32), N % 16 == 0.
// ---------------------------------------------------------------------------
#define BM 128
#define BN 128
#define BK 32
#define AST 36          // smem stride for A and for transposed-B (n-major) tiles
#define BST 136         // smem stride for B (k-major) tiles
#define STG 4608        // floats per smem stage (128*36 == max(32*136,128*36))
#define SMEM_BYTES (4 * STG * 4 * sizeof(float) / 4)  // 2 stages A + 2 stages B
// explicit: 2*STG (A) + 2*STG (B) floats
#define SMEM_TOTAL_BYTES ((size_t)(4 * STG) * sizeof(float))

__device__ __forceinline__ unsigned cvt_tf32(float x) {
    unsigned r;
    asm("cvt.rna.tf32.f32 %0, %1;" : "=r"(r) : "f"(x));
    return r;
}

__device__ __forceinline__ void cp_async16(float* dst, const float* src, bool pred) {
    unsigned d = (unsigned)__cvta_generic_to_shared(dst);
    int sz = pred ? 16 : 0;
    asm volatile("cp.async.cg.shared.global [%0], [%1], 16, %2;"
                 :: "r"(d), "l"(src), "r"(sz));
}

#define CP_COMMIT() asm volatile("cp.async.commit_group;")
#define CP_WAIT0()  asm volatile("cp.async.wait_group 0;")

#define MMA_TF32(d, a, b)                                                     \
    asm volatile(                                                             \
        "mma.sync.aligned.m16n8k8.row.col.f32.tf32.tf32.f32 "                 \
        "{%0,%1,%2,%3},{%4,%5,%6,%7},{%8,%9},{%0,%1,%2,%3};"                  \
        : "+f"((d)[0]), "+f"((d)[1]), "+f"((d)[2]), "+f"((d)[3])              \
        : "r"((a)[0]), "r"((a)[1]), "r"((a)[2]), "r"((a)[3]),                 \
          "r"((b)[0]), "r"((b)[1]))

template <bool TRANSB, bool CAUSAL_SKIP, bool CAUSAL_K>
__global__ __launch_bounds__(256) void mma_gemm(
    const float* __restrict__ A, int lda, long long strideA,
    const float* __restrict__ B, int ldb, long long strideB,
    float* __restrict__ C, int ldc, long long strideC,
    int M, int N, int K, float alpha)
{
    const int bm = blockIdx.y * BM;
    const int bn = blockIdx.x * BN;
    if (CAUSAL_SKIP && bn >= bm + BM) return;   // fully masked tile

    const int batch = blockIdx.z;
    A += (long long)batch * strideA;
    B += (long long)batch * strideB;
    C += (long long)batch * strideC;

    int Keff = K;
    if (CAUSAL_K) Keff = min(K, bm + BM);
    const int niter = Keff / BK;

    extern __shared__ float smem[];
    float* As = smem;               // [2][STG]
    float* Bs = smem + 2 * STG;     // [2][STG]

    const int tid  = threadIdx.x;
    const int lane = tid & 31;
    const int wid  = tid >> 5;
    const int wm   = wid & 3;       // 0..3  -> warp row block of 32
    const int wn   = wid >> 2;      // 0..1  -> warp col block of 64

    float acc[2][8][4];
#pragma unroll
    for (int mt = 0; mt < 2; mt++)
#pragma unroll
        for (int nt = 0; nt < 8; nt++)
#pragma unroll
            for (int i = 0; i < 4; i++) acc[mt][nt][i] = 0.f;

    // ---- tile loaders ----
    auto load_A = [&](int stage, int k0) {
#pragma unroll
        for (int p = 0; p < 4; p++) {
            int lin = p * 256 + tid;
            int r = lin >> 3, cq = lin & 7;
            cp_async16(As + stage * STG + r * AST + cq * 4,
                       A + (long long)(bm + r) * lda + k0 + cq * 4, true);
        }
    };
    auto load_B = [&](int stage, int k0) {
        if (TRANSB) {
            // B is [N,K] row-major; store tile n-major: Bs[n][k], stride AST
#pragma unroll
            for (int p = 0; p < 4; p++) {
                int lin = p * 256 + tid;
                int r = lin >> 3, cq = lin & 7;   // r = n within tile
                bool pred = (bn + r) < N;
                int rs = pred ? r : 0;
                cp_async16(Bs + stage * STG + r * AST + cq * 4,
                           B + (long long)(bn + rs) * ldb + k0 + cq * 4, pred);
            }
        } else {
            // B is [K,N] row-major; store tile k-major: Bs[k][n], stride BST
#pragma unroll
            for (int p = 0; p < 4; p++) {
                int r = p * 8 + (tid >> 5), cq = tid & 31;
                bool pred = (bn + cq * 4) < N;
                cp_async16(Bs + stage * STG + r * BST + cq * 4,
                           B + (long long)(k0 + r) * ldb + bn + cq * 4, pred);
            }
        }
    };

    // ---- pipeline prologue ----
    load_A(0, 0);
    load_B(0, 0);
    CP_COMMIT();
    CP_WAIT0();
    __syncthreads();

    // ---- main loop ----
    for (int it = 0; it < niter; it++) {
        const int cur = it & 1;
        if (it + 1 < niter) {
            load_A(1 - cur, (it + 1) * BK);
            load_B(1 - cur, (it + 1) * BK);
            CP_COMMIT();
        }

        const float* Asb = As + cur * STG;
        const float* Bsb = Bs + cur * STG;

#pragma unroll
        for (int ks = 0; ks < BK / 8; ks++) {
            const int kq = ks * 8 + (lane & 3);
            unsigned af[2][4];
#pragma unroll
            for (int mt = 0; mt < 2; mt++) {
                int m0 = wm * 32 + mt * 16 + (lane >> 2);
                af[mt][0] = cvt_tf32(Asb[m0 * AST + kq]);
                af[mt][1] = cvt_tf32(Asb[(m0 + 8) * AST + kq]);
                af[mt][2] = cvt_tf32(Asb[m0 * AST + kq + 4]);
                af[mt][3] = cvt_tf32(Asb[(m0 + 8) * AST + kq + 4]);
            }
            unsigned bf[8][2];
#pragma unroll
            for (int nt = 0; nt < 8; nt++) {
                int n0 = wn * 64 + nt * 8 + (lane >> 2);
                if (TRANSB) {
                    bf[nt][0] = cvt_tf32(Bsb[n0 * AST + kq]);
                    bf[nt][1] = cvt_tf32(Bsb[n0 * AST + kq + 4]);
                } else {
                    bf[nt][0] = cvt_tf32(Bsb[kq * BST + n0]);
                    bf[nt][1] = cvt_tf32(Bsb[(kq + 4) * BST + n0]);
                }
            }
#pragma unroll
            for (int mt = 0; mt < 2; mt++)
#pragma unroll
                for (int nt = 0; nt < 8; nt++)
                    MMA_TF32(acc[mt][nt], af[mt], bf[nt]);
        }

        if (it + 1 < niter) CP_WAIT0();
        __syncthreads();
    }

    // ---- epilogue ----
#pragma unroll
    for (int mt = 0; mt < 2; mt++) {
        int r0 = bm + wm * 32 + mt * 16 + (lane >> 2);
#pragma unroll
        for (int nt = 0; nt < 8; nt++) {
            int c0 = bn + wn * 64 + nt * 8 + (lane & 3) * 2;
            if (c0 < N) {
                float2 v0 = make_float2(acc[mt][nt][0] * alpha,
                                        acc[mt][nt][1] * alpha);
                float2 v1 = make_float2(acc[mt][nt][2] * alpha,
                                        acc[mt][nt][3] * alpha);
                *reinterpret_cast<float2*>(C + (long long)r0 * ldc + c0) = v0;
                *reinterpret_cast<float2*>(C + (long long)(r0 + 8) * ldc + c0) = v1;
            }
        }
    }
}

// ---------------------------------------------------------------------------
// RMSNorm: one block per row
// ---------------------------------------------------------------------------
__global__ __launch_bounds__(256) void rmsnorm_kernel(
    const float* __restrict__ in, int ldin,
    float* __restrict__ out, int ldout,
    const float* __restrict__ w, int cols)
{
    const int r = blockIdx.x;
    const float* x = in + (long long)r * ldin;
    float ss = 0.f;
    for (int c = threadIdx.x; c < cols; c += blockDim.x) {
        float v = x[c];
        ss += v * v;
    }
    __shared__ float sh[256];
    sh[threadIdx.x] = ss;
    __syncthreads();
    for (int s = 128; s > 0; s >>= 1) {
        if (threadIdx.x < s) sh[threadIdx.x] += sh[threadIdx.x + s];
        __syncthreads();
    }
    float scale = rsqrtf(sh[0] / (float)cols + EPSV);
    for (int c = threadIdx.x; c < cols; c += blockDim.x)
        out[(long long)r * ldout + c] = x[c] * scale * w[c];
}

// ---------------------------------------------------------------------------
// RoPE (interleaved): rotates q's rope part in place, emits rotated k_rope.
// ---------------------------------------------------------------------------
__global__ __launch_bounds__(512) void rope_kernel(
    float* __restrict__ q, const float* __restrict__ kvc,
    float* __restrict__ krope, const int* __restrict__ positions)
{
    const int s = blockIdx.x;
    const int t = threadIdx.x;
    const int h = t >> 5;
    const int i = t & 31;

    float pos = (float)positions[s];
    float inv = powf(10000.0f, -(2.0f * (float)i) / (float)ROPE);
    float ang = pos * inv;
    float sn, cs;
    sincosf(ang, &sn, &cs);

    float* qp = q + ((long long)s * NH + h) * QK + NOPE + 2 * i;
    float x1 = qp[0], x2 = qp[1];
    qp[0] = x1 * cs - x2 * sn;
    qp[1] = x2 * cs + x1 * sn;

    if (h == 0) {
        const float* kp = kvc + (long long)s * (KV_LORA + ROPE) + KV_LORA + 2 * i;
        float y1 = kp[0], y2 = kp[1];
        krope[(long long)s * ROPE + 2 * i]     = y1 * cs - y2 * sn;
        krope[(long long)s * ROPE + 2 * i + 1] = y2 * cs + y1 * sn;
    }
}

// ---------------------------------------------------------------------------
// Assemble k_full[s][h][0:192] = k_nope[s][h][0:128] | k_rope_rot[s][0:64]
// ---------------------------------------------------------------------------
__global__ __launch_bounds__(256) void kfull_kernel(
    const float* __restrict__ kv, const float* __restrict__ krope,
    float* __restrict__ kfull)
{
    long long idx = (long long)blockIdx.x * blockDim.x + threadIdx.x;
    const long long total = (long long)S * NH * QK;
    if (idx >= total) return;
    int d = (int)(idx % QK);
    long long sh = idx / QK;
    int h = (int)(sh % NH);
    long long s = sh / NH;
    kfull[idx] = (d < NOPE) ? kv[(s * NH + h) * KVD + d]
                            : krope[s * ROPE + (d - NOPE)];
}

// ---------------------------------------------------------------------------
// Causal softmax over scores[h][s][*]: in place; zeros past the diagonal.
// ---------------------------------------------------------------------------
__global__ __launch_bounds__(256) void softmax_kernel(float* __restrict__ scores)
{
    const int s = blockIdx.x;
    const int h = blockIdx.y;
    float* row = scores + ((long long)h * S + s) * S;
    const int L = s + 1;
    __shared__ float sh[256];

    float m = -3.4e38f;
    for (int t = threadIdx.x; t < L; t += blockDim.x) m = fmaxf(m, row[t]);
    sh[threadIdx.x] = m;
    __syncthreads();
    for (int k = 128; k > 0; k >>= 1) {
        if (threadIdx.x < k) sh[threadIdx.x] = fmaxf(sh[threadIdx.x], sh[threadIdx.x + k]);
        __syncthreads();
    }
    m = sh[0];
    __syncthreads();

    float sum = 0.f;
    for (int t = threadIdx.x; t < L; t += blockDim.x) {
        float e = __expf(row[t] - m);
        row[t] = e;
        sum += e;
    }
    sh[threadIdx.x] = sum;
    __syncthreads();
    for (int k = 128; k > 0; k >>= 1) {
        if (threadIdx.x < k) sh[threadIdx.x] += sh[threadIdx.x + k];
        __syncthreads();
    }
    float inv = 1.0f / sh[0];

    for (int t = threadIdx.x; t < S; t += blockDim.x)
        row[t] = (t < L) ? row[t] * inv : 0.f;
}

// ---------------------------------------------------------------------------
// Host launcher
// ---------------------------------------------------------------------------
static inline void* sym_addr(const void* symbol)
{
    void* p = nullptr;
    cudaGetSymbolAddress(&p, symbol);
    return p;
}

extern "C" void kernel_launch(void* const* d_in, const int* in_sizes, int n_in,
                              void* d_out, int out_size)
{
    const float* hidden  = (const float*)d_in[0];
    const float* w_qa    = (const float*)d_in[1];
    const float* qa_ln_w = (const float*)d_in[2];
    const float* w_qb    = (const float*)d_in[3];
    const float* w_kva   = (const float*)d_in[4];
    const float* kva_ln_w= (const float*)d_in[5];
    const float* w_kvb   = (const float*)d_in[6];
    const float* w_o     = (const float*)d_in[7];
    const int*   positions = (const int*)d_in[8];
    float* out = (float*)d_out;

    float* qc     = (float*)sym_addr(g_qc);
    float* q      = (float*)sym_addr(g_q);
    float* kvc    = (float*)sym_addr(g_kvc);
    float* kvlat  = (float*)sym_addr(g_kvlat);
    float* kv     = (float*)sym_addr(g_kv);
    float* krope  = (float*)sym_addr(g_krope);
    float* kfull  = (float*)sym_addr(g_kfull);
    float* scores = (float*)sym_addr(g_scores);
    float* attn   = (float*)sym_addr(g_attn);

    const dim3 blk(256);
    const size_t smem = SMEM_TOTAL_BYTES;

    cudaFuncSetAttribute(mma_gemm<false, false, false>,
                         cudaFuncAttributeMaxDynamicSharedMemorySize, (int)smem);
    cudaFuncSetAttribute(mma_gemm<true, true, false>,
                         cudaFuncAttributeMaxDynamicSharedMemorySize, (int)smem);
    cudaFuncSetAttribute(mma_gemm<false, false, true>,
                         cudaFuncAttributeMaxDynamicSharedMemorySize, (int)smem);

    // 1. q_c_raw = hidden @ w_qa            [2048,1536] K=2048
    mma_gemm<false, false, false><<<dim3(Q_LORA / BN, S / BM, 1), blk, smem>>>(
        hidden, HIDDEN, 0, w_qa, Q_LORA, 0, qc, Q_LORA, 0,
        S, Q_LORA, HIDDEN, 1.0f);

    // 2. rmsnorm(q_c) in place
    rmsnorm_kernel<<<S, blk>>>(qc, Q_LORA, qc, Q_LORA, qa_ln_w, Q_LORA);

    // 3. q = q_c @ w_qb                     [2048,3072] K=1536
    mma_gemm<false, false, false><<<dim3((NH * QK) / BN, S / BM, 1), blk, smem>>>(
        qc, Q_LORA, 0, w_qb, NH * QK, 0, q, NH * QK, 0,
        S, NH * QK, Q_LORA, 1.0f);

    // 4. kv_c = hidden @ w_kva              [2048,576] K=2048 (partial N tile)
    mma_gemm<false, false, false><<<dim3((KV_LORA + ROPE + BN - 1) / BN, S / BM, 1), blk, smem>>>(
        hidden, HIDDEN, 0, w_kva, KV_LORA + ROPE, 0, kvc, KV_LORA + ROPE, 0,
        S, KV_LORA + ROPE, HIDDEN, 1.0f);

    // 5. kv_lat = rmsnorm(kv_c[:, :512])
    rmsnorm_kernel<<<S, blk>>>(kvc, KV_LORA + ROPE, kvlat, KV_LORA, kva_ln_w, KV_LORA);

    // 6. kv = kv_lat @ w_kvb                [2048,4096] K=512
    mma_gemm<false, false, false><<<dim3((NH * KVD) / BN, S / BM, 1), blk, smem>>>(
        kvlat, KV_LORA, 0, w_kvb, NH * KVD, 0, kv, NH * KVD, 0,
        S, NH * KVD, KV_LORA, 1.0f);

    // 7. RoPE (q in place; k_rope -> krope)
    rope_kernel<<<S, 512>>>(q, kvc, krope, positions);

    // 8. assemble k_full
    {
        long long total = (long long)S * NH * QK;
        int nb = (int)((total + 255) / 256);
        kfull_kernel<<<nb, blk>>>(kv, krope, kfull);
    }

    // 9. scores[h] = (Q_h @ K_h^T) * scale   batched NT, causal tile skip
    const float scale = 1.0f / sqrtf((float)QK);
    mma_gemm<true, true, false><<<dim3(S / BN, S / BM, NH), blk, smem>>>(
        q, NH * QK, QK,
        kfull, NH * QK, QK,
        scores, S, (long long)S * S,
        S, S, QK, scale);

    // 10. causal softmax in place (writes zeros past the diagonal)
    softmax_kernel<<<dim3(S, NH), blk>>>(scores);

    // 11. attn[h] = probs[h] @ V_h           batched NN, causal-K truncation
    mma_gemm<false, false, true><<<dim3(V_DIM / BN, S / BM, NH), blk, smem>>>(
        scores, S, (long long)S * S,
        kv + NOPE, NH * KVD, KVD,
        attn, NH * V_DIM, V_DIM,
        S, V_DIM, S, 1.0f);

    // 12. out = attn @ w_o                   [2048,2048] K=2048
    mma_gemm<false, false, false><<<dim3(HIDDEN / BN, S / BM, 1), blk, smem>>>(
        attn, NH * V_DIM, 0, w_o, HIDDEN, 0, out, HIDDEN, 0,
        S, HIDDEN, NH * V_DIM, 1.0f);
}

// round 4
// speedup vs baseline: 3.3048x; 1.1306x over previous
#include <cuda_runtime.h>
#include <cuda_bf16.h>
#include <math.h>

// ---------------------------------------------------------------------------
// Problem constants
// ---------------------------------------------------------------------------
#define S 2048
#define HIDDEN 2048
#define Q_LORA 1536
#define KV_LORA 512
#define NOPE 128
#define ROPE 64
#define V_DIM 128
#define NH 16
#define QK 192          // NOPE + ROPE
#define KVD 256         // NOPE + V_DIM
#define EPSV 1e-6f

// ---------------------------------------------------------------------------
// Scratch (static device globals)
// ---------------------------------------------------------------------------
__device__ float g_qc    [(size_t)S * Q_LORA];
__device__ float g_q     [(size_t)S * NH * QK];
__device__ float g_kvc   [(size_t)S * (KV_LORA + ROPE)];
__device__ float g_kvlat [(size_t)S * KV_LORA];
__device__ float g_kv    [(size_t)S * NH * KVD];
__device__ float g_krope [(size_t)S * ROPE];
__device__ float g_kfull [(size_t)S * NH * QK];
__device__ float g_scores[(size_t)NH * S * S];
__device__ float g_attn  [(size_t)S * NH * V_DIM];

// ---------------------------------------------------------------------------
// tf32 tensor-core GEMM: C[M,N] = alpha * A[M,K] @ op(B), row-major.
// TRANSB:      B is [N,K] row-major (C = alpha * A @ B^T)
// CAUSAL_SKIP: skip CTA tiles strictly above the diagonal
// CAUSAL_K:    truncate K loop at bm+BM
//
// CTA tile 128 x BNv x 32, 256 threads = 8 warps (4m x 2n),
// warp tile 32 x (BNv/2), m16n8k8 tf32 mma.sync.
// 3-stage cp.async pipeline, 2 CTAs/SM.
// Requirements: M % 128 == 0, Keff % 32 == 0.
// ---------------------------------------------------------------------------
#define BM 128
#define BK 32
#define AST 36                   // smem stride for A / transposed-B (n-major)
#define ASTG (BM * AST)          // 4608 floats per A stage
#define NSTAGE 3

__device__ __forceinline__ unsigned cvt_tf32(float x) {
    unsigned r;
    asm("cvt.rna.tf32.f32 %0, %1;" : "=r"(r) : "f"(x));
    return r;
}

__device__ __forceinline__ void cp_async16(float* dst, const float* src, bool pred) {
    unsigned d = (unsigned)__cvta_generic_to_shared(dst);
    int sz = pred ? 16 : 0;
    asm volatile("cp.async.cg.shared.global [%0], [%1], 16, %2;"
                 :: "r"(d), "l"(src), "r"(sz));
}

#define CP_COMMIT() asm volatile("cp.async.commit_group;")
#define CP_WAIT0()  asm volatile("cp.async.wait_group 0;")
#define CP_WAIT1()  asm volatile("cp.async.wait_group 1;")

#define MMA_TF32(d, a, b)                                                     \
    asm volatile(                                                             \
        "mma.sync.aligned.m16n8k8.row.col.f32.tf32.tf32.f32 "                 \
        "{%0,%1,%2,%3},{%4,%5,%6,%7},{%8,%9},{%0,%1,%2,%3};"                  \
        : "+f"((d)[0]), "+f"((d)[1]), "+f"((d)[2]), "+f"((d)[3])              \
        : "r"((a)[0]), "r"((a)[1]), "r"((a)[2]), "r"((a)[3]),                 \
          "r"((b)[0]), "r"((b)[1]))

template <int BNv, bool TRANSB, bool CAUSAL_SKIP, bool CAUSAL_K>
__global__ __launch_bounds__(256, 2) void mma_gemm(
    const float* __restrict__ A, int lda, long long strideA,
    const float* __restrict__ B, int ldb, long long strideB,
    float* __restrict__ C, int ldc, long long strideC,
    int M, int N, int K, float alpha)
{
    constexpr int NT   = BNv / 16;                 // n-tiles per warp
    constexpr int BST  = BNv + 8;                  // k-major B smem stride
    constexpr int BSTG = TRANSB ? BNv * AST : BK * BST;

    const int bm = blockIdx.y * BM;
    const int bn = blockIdx.x * BNv;
    if (CAUSAL_SKIP && bn >= bm + BM) return;

    const int batch = blockIdx.z;
    A += (long long)batch * strideA;
    B += (long long)batch * strideB;
    C += (long long)batch * strideC;

    int Keff = K;
    if (CAUSAL_K) Keff = min(K, bm + BM);
    const int niter = Keff / BK;

    extern __shared__ float smem[];
    float* As = smem;                     // [NSTAGE][ASTG]
    float* Bs = smem + NSTAGE * ASTG;     // [NSTAGE][BSTG]

    const int tid  = threadIdx.x;
    const int lane = tid & 31;
    const int wid  = tid >> 5;
    const int wm   = wid & 3;             // warp row block (32 rows)
    const int wn   = wid >> 2;            // warp col block (BNv/2 cols)

    float acc[2][NT][4];
#pragma unroll
    for (int mt = 0; mt < 2; mt++)
#pragma unroll
        for (int nt = 0; nt < NT; nt++)
#pragma unroll
            for (int i = 0; i < 4; i++) acc[mt][nt][i] = 0.f;

    auto load_A = [&](int stage, int k0) {
#pragma unroll
        for (int p = 0; p < 4; p++) {
            int lin = p * 256 + tid;
            int r = lin >> 3, cq = lin & 7;
            cp_async16(As + stage * ASTG + r * AST + cq * 4,
                       A + (long long)(bm + r) * lda + k0 + cq * 4, true);
        }
    };
    auto load_B = [&](int stage, int k0) {
        if (TRANSB) {
            // B [N,K] row-major -> n-major tile Bs[n][k], stride AST
#pragma unroll
            for (int p = 0; p < BNv / 32; p++) {
                int lin = p * 256 + tid;
                int r = lin >> 3, cq = lin & 7;
                bool pred = (bn + r) < N;
                int rs = pred ? r : 0;
                cp_async16(Bs + stage * BSTG + r * AST + cq * 4,
                           B + (long long)(bn + rs) * ldb + k0 + cq * 4, pred);
            }
        } else {
            // B [K,N] row-major -> k-major tile Bs[k][n], stride BST
#pragma unroll
            for (int p = 0; p < BNv / 32; p++) {
                int lin = p * 256 + tid;
                int r = lin / (BNv / 4);
                int cq = lin % (BNv / 4);
                bool pred = (bn + cq * 4) < N;
                cp_async16(Bs + stage * BSTG + r * BST + cq * 4,
                           B + (long long)(k0 + r) * ldb + bn + cq * 4, pred);
            }
        }
    };

    // ---- pipeline prologue: stages 0 and 1 in flight ----
    load_A(0, 0); load_B(0, 0); CP_COMMIT();
    if (niter > 1) { load_A(1, BK); load_B(1, BK); CP_COMMIT(); }

    // ---- main loop: one __syncthreads per iteration ----
    for (int it = 0; it < niter; it++) {
        if (it + 1 < niter) CP_WAIT1(); else CP_WAIT0();
        __syncthreads();

        if (it + 2 < niter) {
            int stg = (it + 2) % NSTAGE;
            load_A(stg, (it + 2) * BK);
            load_B(stg, (it + 2) * BK);
            CP_COMMIT();
        }

        const int cur = it % NSTAGE;
        const float* Asb = As + cur * ASTG;
        const float* Bsb = Bs + cur * BSTG;

#pragma unroll
        for (int ks = 0; ks < BK / 8; ks++) {
            const int kq = ks * 8 + (lane & 3);
            unsigned af[2][4];
#pragma unroll
            for (int mt = 0; mt < 2; mt++) {
                int m0 = wm * 32 + mt * 16 + (lane >> 2);
                af[mt][0] = cvt_tf32(Asb[m0 * AST + kq]);
                af[mt][1] = cvt_tf32(Asb[(m0 + 8) * AST + kq]);
                af[mt][2] = cvt_tf32(Asb[m0 * AST + kq + 4]);
                af[mt][3] = cvt_tf32(Asb[(m0 + 8) * AST + kq + 4]);
            }
            unsigned bf[NT][2];
#pragma unroll
            for (int nt = 0; nt < NT; nt++) {
                int n0 = wn * (BNv / 2) + nt * 8 + (lane >> 2);
                if (TRANSB) {
                    bf[nt][0] = cvt_tf32(Bsb[n0 * AST + kq]);
                    bf[nt][1] = cvt_tf32(Bsb[n0 * AST + kq + 4]);
                } else {
                    bf[nt][0] = cvt_tf32(Bsb[kq * BST + n0]);
                    bf[nt][1] = cvt_tf32(Bsb[(kq + 4) * BST + n0]);
                }
            }
#pragma unroll
            for (int mt = 0; mt < 2; mt++)
#pragma unroll
                for (int nt = 0; nt < NT; nt++)
                    MMA_TF32(acc[mt][nt], af[mt], bf[nt]);
        }
    }

    // ---- epilogue ----
#pragma unroll
    for (int mt = 0; mt < 2; mt++) {
        int r0 = bm + wm * 32 + mt * 16 + (lane >> 2);
#pragma unroll
        for (int nt = 0; nt < NT; nt++) {
            int c0 = bn + wn * (BNv / 2) + nt * 8 + (lane & 3) * 2;
            if (c0 < N) {
                float2 v0 = make_float2(acc[mt][nt][0] * alpha,
                                        acc[mt][nt][1] * alpha);
                float2 v1 = make_float2(acc[mt][nt][2] * alpha,
                                        acc[mt][nt][3] * alpha);
                *reinterpret_cast<float2*>(C + (long long)r0 * ldc + c0) = v0;
                *reinterpret_cast<float2*>(C + (long long)(r0 + 8) * ldc + c0) = v1;
            }
        }
    }
}

// ---------------------------------------------------------------------------
// RMSNorm: one block per row
// ---------------------------------------------------------------------------
__global__ __launch_bounds__(256) void rmsnorm_kernel(
    const float* __restrict__ in, int ldin,
    float* __restrict__ out, int ldout,
    const float* __restrict__ w, int cols)
{
    const int r = blockIdx.x;
    const float* x = in + (long long)r * ldin;
    float ss = 0.f;
    for (int c = threadIdx.x; c < cols; c += blockDim.x) {
        float v = x[c];
        ss += v * v;
    }
    __shared__ float sh[256];
    sh[threadIdx.x] = ss;
    __syncthreads();
    for (int s = 128; s > 0; s >>= 1) {
        if (threadIdx.x < s) sh[threadIdx.x] += sh[threadIdx.x + s];
        __syncthreads();
    }
    float scale = rsqrtf(sh[0] / (float)cols + EPSV);
    for (int c = threadIdx.x; c < cols; c += blockDim.x)
        out[(long long)r * ldout + c] = x[c] * scale * w[c];
}

// ---------------------------------------------------------------------------
// RoPE (interleaved)
// ---------------------------------------------------------------------------
__global__ __launch_bounds__(512) void rope_kernel(
    float* __restrict__ q, const float* __restrict__ kvc,
    float* __restrict__ krope, const int* __restrict__ positions)
{
    const int s = blockIdx.x;
    const int t = threadIdx.x;
    const int h = t >> 5;
    const int i = t & 31;

    float pos = (float)positions[s];
    float inv = powf(10000.0f, -(2.0f * (float)i) / (float)ROPE);
    float ang = pos * inv;
    float sn, cs;
    sincosf(ang, &sn, &cs);

    float* qp = q + ((long long)s * NH + h) * QK + NOPE + 2 * i;
    float x1 = qp[0], x2 = qp[1];
    qp[0] = x1 * cs - x2 * sn;
    qp[1] = x2 * cs + x1 * sn;

    if (h == 0) {
        const float* kp = kvc + (long long)s * (KV_LORA + ROPE) + KV_LORA + 2 * i;
        float y1 = kp[0], y2 = kp[1];
        krope[(long long)s * ROPE + 2 * i]     = y1 * cs - y2 * sn;
        krope[(long long)s * ROPE + 2 * i + 1] = y2 * cs + y1 * sn;
    }
}

// ---------------------------------------------------------------------------
// Assemble k_full
// ---------------------------------------------------------------------------
__global__ __launch_bounds__(256) void kfull_kernel(
    const float* __restrict__ kv, const float* __restrict__ krope,
    float* __restrict__ kfull)
{
    long long idx = (long long)blockIdx.x * blockDim.x + threadIdx.x;
    const long long total = (long long)S * NH * QK;
    if (idx >= total) return;
    int d = (int)(idx % QK);
    long long sh = idx / QK;
    int h = (int)(sh % NH);
    long long s = sh / NH;
    kfull[idx] = (d < NOPE) ? kv[(s * NH + h) * KVD + d]
                            : krope[s * ROPE + (d - NOPE)];
}

// ---------------------------------------------------------------------------
// Causal softmax; zero-fills only to the next BM boundary (PV's causal-K
// truncation never reads past it).
// ---------------------------------------------------------------------------
__global__ __launch_bounds__(256) void softmax_kernel(float* __restrict__ scores)
{
    const int s = blockIdx.x;
    const int h = blockIdx.y;
    float* row = scores + ((long long)h * S + s) * S;
    const int L = s + 1;
    const int Lpad = (s / BM + 1) * BM;
    __shared__ float sh[256];

    float m = -3.4e38f;
    for (int t = threadIdx.x; t < L; t += blockDim.x) m = fmaxf(m, row[t]);
    sh[threadIdx.x] = m;
    __syncthreads();
    for (int k = 128; k > 0; k >>= 1) {
        if (threadIdx.x < k) sh[threadIdx.x] = fmaxf(sh[threadIdx.x], sh[threadIdx.x + k]);
        __syncthreads();
    }
    m = sh[0];
    __syncthreads();

    float sum = 0.f;
    for (int t = threadIdx.x; t < L; t += blockDim.x) {
        float e = __expf(row[t] - m);
        row[t] = e;
        sum += e;
    }
    sh[threadIdx.x] = sum;
    __syncthreads();
    for (int k = 128; k > 0; k >>= 1) {
        if (threadIdx.x < k) sh[threadIdx.x] += sh[threadIdx.x + k];
        __syncthreads();
    }
    float inv = 1.0f / sh[0];

    for (int t = threadIdx.x; t < Lpad; t += blockDim.x)
        row[t] = (t < L) ? row[t] * inv : 0.f;
}

// ---------------------------------------------------------------------------
// Host launcher
// ---------------------------------------------------------------------------
static inline void* sym_addr(const void* symbol)
{
    void* p = nullptr;
    cudaGetSymbolAddress(&p, symbol);
    return p;
}

extern "C" void kernel_launch(void* const* d_in, const int* in_sizes, int n_in,
                              void* d_out, int out_size)
{
    const float* hidden  = (const float*)d_in[0];
    const float* w_qa    = (const float*)d_in[1];
    const float* qa_ln_w = (const float*)d_in[2];
    const float* w_qb    = (const float*)d_in[3];
    const float* w_kva   = (const float*)d_in[4];
    const float* kva_ln_w= (const float*)d_in[5];
    const float* w_kvb   = (const float*)d_in[6];
    const float* w_o     = (const float*)d_in[7];
    const int*   positions = (const int*)d_in[8];
    float* out = (float*)d_out;

    float* qc     = (float*)sym_addr(g_qc);
    float* q      = (float*)sym_addr(g_q);
    float* kvc    = (float*)sym_addr(g_kvc);
    float* kvlat  = (float*)sym_addr(g_kvlat);
    float* kv     = (float*)sym_addr(g_kv);
    float* krope  = (float*)sym_addr(g_krope);
    float* kfull  = (float*)sym_addr(g_kfull);
    float* scores = (float*)sym_addr(g_scores);
    float* attn   = (float*)sym_addr(g_attn);

    const dim3 blk(256);

    // smem sizes per instantiation
    const size_t smem_nn128 = (size_t)NSTAGE * (ASTG + BK * (128 + 8)) * 4; // 107,520
    const size_t smem_nn64  = (size_t)NSTAGE * (ASTG + BK * (64 + 8))  * 4; //  82,944
    const size_t smem_tt128 = (size_t)NSTAGE * (ASTG + 128 * AST)      * 4; // 110,592

    cudaFuncSetAttribute(mma_gemm<128, false, false, false>,
                         cudaFuncAttributeMaxDynamicSharedMemorySize, (int)smem_nn128);
    cudaFuncSetAttribute(mma_gemm<64, false, false, false>,
                         cudaFuncAttributeMaxDynamicSharedMemorySize, (int)smem_nn64);
    cudaFuncSetAttribute(mma_gemm<128, true, true, false>,
                         cudaFuncAttributeMaxDynamicSharedMemorySize, (int)smem_tt128);
    cudaFuncSetAttribute(mma_gemm<128, false, false, true>,
                         cudaFuncAttributeMaxDynamicSharedMemorySize, (int)smem_nn128);

    // 1. q_c_raw = hidden @ w_qa            [2048,1536] K=2048
    mma_gemm<128, false, false, false><<<dim3(Q_LORA / 128, S / BM, 1), blk, smem_nn128>>>(
        hidden, HIDDEN, 0, w_qa, Q_LORA, 0, qc, Q_LORA, 0,
        S, Q_LORA, HIDDEN, 1.0f);

    // 2. rmsnorm(q_c) in place
    rmsnorm_kernel<<<S, blk>>>(qc, Q_LORA, qc, Q_LORA, qa_ln_w, Q_LORA);

    // 3. q = q_c @ w_qb                     [2048,3072] K=1536
    mma_gemm<128, false, false, false><<<dim3((NH * QK) / 128, S / BM, 1), blk, smem_nn128>>>(
        qc, Q_LORA, 0, w_qb, NH * QK, 0, q, NH * QK, 0,
        S, NH * QK, Q_LORA, 1.0f);

    // 4. kv_c = hidden @ w_kva              [2048,576] K=2048, BN=64 tiles
    mma_gemm<64, false, false, false><<<dim3((KV_LORA + ROPE + 63) / 64, S / BM, 1), blk, smem_nn64>>>(
        hidden, HIDDEN, 0, w_kva, KV_LORA + ROPE, 0, kvc, KV_LORA + ROPE, 0,
        S, KV_LORA + ROPE, HIDDEN, 1.0f);

    // 5. kv_lat = rmsnorm(kv_c[:, :512])
    rmsnorm_kernel<<<S, blk>>>(kvc, KV_LORA + ROPE, kvlat, KV_LORA, kva_ln_w, KV_LORA);

    // 6. kv = kv_lat @ w_kvb                [2048,4096] K=512
    mma_gemm<128, false, false, false><<<dim3((NH * KVD) / 128, S / BM, 1), blk, smem_nn128>>>(
        kvlat, KV_LORA, 0, w_kvb, NH * KVD, 0, kv, NH * KVD, 0,
        S, NH * KVD, KV_LORA, 1.0f);

    // 7. RoPE
    rope_kernel<<<S, 512>>>(q, kvc, krope, positions);

    // 8. assemble k_full
    {
        long long total = (long long)S * NH * QK;
        int nb = (int)((total + 255) / 256);
        kfull_kernel<<<nb, blk>>>(kv, krope, kfull);
    }

    // 9. scores[h] = (Q_h @ K_h^T) * scale
    const float scale = 1.0f / sqrtf((float)QK);
    mma_gemm<128, true, true, false><<<dim3(S / 128, S / BM, NH), blk, smem_tt128>>>(
        q, NH * QK, QK,
        kfull, NH * QK, QK,
        scores, S, (long long)S * S,
        S, S, QK, scale);

    // 10. causal softmax
    softmax_kernel<<<dim3(S, NH), blk>>>(scores);

    // 11. attn[h] = probs[h] @ V_h
    mma_gemm<128, false, false, true><<<dim3(V_DIM / 128, S / BM, NH), blk, smem_nn128>>>(
        scores, S, (long long)S * S,
        kv + NOPE, NH * KVD, KVD,
        attn, NH * V_DIM, V_DIM,
        S, V_DIM, S, 1.0f);

    // 12. out = attn @ w_o                  [2048,2048] K=2048
    mma_gemm<128, false, false, false><<<dim3(HIDDEN / 128, S / BM, 1), blk, smem_nn128>>>(
        attn, NH * V_DIM, 0, w_o, HIDDEN, 0, out, HIDDEN, 0,
        S, HIDDEN, NH * V_DIM, 1.0f);
}